// round 5
// baseline (speedup 1.0000x reference)
#include <cuda_runtime.h>
#include <cooperative_groups.h>
#include <math.h>

namespace cg = cooperative_groups;

#define LSEQ 8192
#define EDIM 256
#define HD 256
#define G4 1024
#define TT 34

// ---------------- static scratch ----------------
__device__ float g_Gx[2][LSEQ * G4];
__device__ float g_hs[2][LSEQ * HD];
__device__ float g_ef[LSEQ * TT + 64];
__device__ float g_aS[LSEQ * TT];
__device__ float g_bS[LSEQ * TT];
__device__ float g_Ka[LSEQ];
__device__ float g_Kb[LSEQ];

// ---------------- helpers ----------------
__device__ __forceinline__ void fma2(unsigned long long& d, unsigned long long a,
                                     unsigned long long b) {
    asm("fma.rn.f32x2 %0, %1, %2, %0;" : "+l"(d) : "l"(a), "l"(b));
}
__device__ __forceinline__ unsigned long long add2(unsigned long long a,
                                                   unsigned long long b) {
    unsigned long long d;
    asm("add.rn.f32x2 %0, %1, %2;" : "=l"(d) : "l"(a), "l"(b));
    return d;
}
__device__ __forceinline__ float hsum2(unsigned long long a) {
    float lo, hi;
    asm("mov.b64 {%0, %1}, %2;" : "=f"(lo), "=f"(hi) : "l"(a));
    return lo + hi;
}
__device__ __forceinline__ float sigm(float x) {
    return __fdividef(1.f, 1.f + __expf(-x));
}
__device__ __forceinline__ float tanh_(float x) {
    float e = __expf(2.f * x);
    return 1.f - __fdividef(2.f, e + 1.f);
}

// ---------------- k0: zero output ----------------
__global__ void k0_fill(float* out, int n) {
    int i = blockIdx.x * blockDim.x + threadIdx.x;
    if (i < n) out[i] = 0.f;
}

// ---------------- k1: input projection GEMM ----------------
__global__ __launch_bounds__(256) void k1_gx(
    const int* __restrict__ words, const float* __restrict__ embed,
    const float* __restrict__ Wih_f, const float* __restrict__ b_f,
    const float* __restrict__ Wih_b, const float* __restrict__ b_b) {
    int dir = blockIdx.z;
    const float* Wih = dir ? Wih_b : Wih_f;
    const float* bias = dir ? b_b : b_f;
    int t0 = blockIdx.x * 64, r0 = blockIdx.y * 64;

    __shared__ int ws_[64];
    __shared__ __align__(16) float sx[32][68];
    __shared__ __align__(16) float sw[32][68];

    int tid = threadIdx.x;
    int tx = tid & 15, ty = tid >> 4;
    if (tid < 64) ws_[tid] = words[t0 + tid];
    __syncthreads();

    float acc[4][4];
#pragma unroll
    for (int i = 0; i < 4; i++)
#pragma unroll
        for (int j = 0; j < 4; j++) acc[i][j] = 0.f;

    for (int k0 = 0; k0 < EDIM; k0 += 32) {
#pragma unroll
        for (int rep = 0; rep < 2; rep++) {
            int lin = tid + rep * 256;
            int row = lin >> 3;
            int kq = lin & 7;
            float4 xv = *(const float4*)&embed[(size_t)ws_[row] * EDIM + k0 + kq * 4];
            sx[kq * 4 + 0][row] = xv.x; sx[kq * 4 + 1][row] = xv.y;
            sx[kq * 4 + 2][row] = xv.z; sx[kq * 4 + 3][row] = xv.w;
            float4 wv = *(const float4*)&Wih[(size_t)(r0 + row) * EDIM + k0 + kq * 4];
            sw[kq * 4 + 0][row] = wv.x; sw[kq * 4 + 1][row] = wv.y;
            sw[kq * 4 + 2][row] = wv.z; sw[kq * 4 + 3][row] = wv.w;
        }
        __syncthreads();
#pragma unroll
        for (int kk = 0; kk < 32; kk++) {
            float4 a = *(const float4*)&sx[kk][tx * 4];
            float4 b = *(const float4*)&sw[kk][ty * 4];
            float av[4] = {a.x, a.y, a.z, a.w};
            float bv[4] = {b.x, b.y, b.z, b.w};
#pragma unroll
            for (int i = 0; i < 4; i++)
#pragma unroll
                for (int j = 0; j < 4; j++)
                    acc[i][j] = fmaf(av[i], bv[j], acc[i][j]);
        }
        __syncthreads();
    }
    float bj[4];
#pragma unroll
    for (int j = 0; j < 4; j++) bj[j] = bias[r0 + ty * 4 + j];
    float* outp = g_Gx[dir];
#pragma unroll
    for (int i = 0; i < 4; i++)
#pragma unroll
        for (int j = 0; j < 4; j++)
            outp[(size_t)(t0 + tx * 4 + i) * G4 + (r0 + ty * 4 + j)] = acc[i][j] + bj[j];
}

// ---------------- k2: bidirectional LSTM (2 clusters of 8 CTAs) ----------------
__global__ __launch_bounds__(256, 1) __cluster_dims__(8, 1, 1)
void k2_lstm(const float* __restrict__ Whh_f, const float* __restrict__ Whh_b) {
    cg::cluster_group cluster = cg::this_cluster();
    int rank = (int)cluster.block_rank();
    int dir = (blockIdx.x >= 8) ? 1 : 0;
    const float* Whh = dir ? Whh_b : Whh_f;

    __shared__ __align__(16) float h_buf[2][HD];
    __shared__ float red[256];

    int tid = threadIdx.x;
    int w = tid >> 5, l = tid & 31;
    int g = w & 3, khalf = w >> 2;
    int j0 = rank * 32;
    int R = g * 256 + j0 + l;

    unsigned long long w2[64];
    const unsigned long long* wp =
        (const unsigned long long*)(Whh + (size_t)R * HD + khalf * 128);
#pragma unroll
    for (int k = 0; k < 64; k++) w2[k] = wp[k];

    h_buf[0][tid] = 0.f;
    h_buf[1][tid] = 0.f;
    float c = 0.f;
    const float* Gx = g_Gx[dir];
    float* hsout = g_hs[dir];
    cluster.sync();

    int buf = 0;
    for (int t = 0; t < LSEQ; t++) {
        int tt = dir ? (LSEQ - 1 - t) : t;

        float gx0 = 0.f, gx1 = 0.f, gx2 = 0.f, gx3 = 0.f;
        if (w == 0) {
            const float* gp = Gx + (size_t)tt * G4 + j0 + l;
            gx0 = gp[0]; gx1 = gp[256]; gx2 = gp[512]; gx3 = gp[768];
        }

        const unsigned long long* hp =
            (const unsigned long long*)&h_buf[buf][khalf * 128];
        unsigned long long a0 = 0ull, a1 = 0ull, a2 = 0ull, a3 = 0ull;
#pragma unroll
        for (int k = 0; k < 64; k += 4) {
            fma2(a0, w2[k + 0], hp[k + 0]);
            fma2(a1, w2[k + 1], hp[k + 1]);
            fma2(a2, w2[k + 2], hp[k + 2]);
            fma2(a3, w2[k + 3], hp[k + 3]);
        }
        red[tid] = hsum2(add2(add2(a0, a1), add2(a2, a3)));
        __syncthreads();

        if (w == 0) {
            float gi = red[l]       + red[128 + l] + gx0;
            float gf = red[32 + l]  + red[160 + l] + gx1;
            float gg = red[64 + l]  + red[192 + l] + gx2;
            float go = red[96 + l]  + red[224 + l] + gx3;
            float i_ = sigm(gi), f_ = sigm(gf), g_ = tanh_(gg), o_ = sigm(go);
            c = f_ * c + i_ * g_;
            float h = o_ * tanh_(c);
            hsout[(size_t)tt * HD + j0 + l] = h;
            int nxt = buf ^ 1;
#pragma unroll
            for (int p = 0; p < 8; p++) {
                float* dst = cluster.map_shared_rank(&h_buf[nxt][j0 + l], p);
                *dst = h;
            }
        }
        cluster.sync();
        buf ^= 1;
    }
}

// ---------------- k3: feats + exp ----------------
__global__ __launch_bounds__(64) void k3_feats(const float* __restrict__ W_out,
                                               const float* __restrict__ b_out) {
    int t = blockIdx.x;
    __shared__ float ls[512];
    int tid = threadIdx.x;
#pragma unroll
    for (int r = 0; r < 8; r++) {
        int i = tid + r * 64;
        ls[i] = (i < 256) ? g_hs[0][(size_t)t * HD + i]
                          : g_hs[1][(size_t)t * HD + (i - 256)];
    }
    __syncthreads();
    if (tid < TT) {
        const float* wr = W_out + tid * 512;
        float a0 = 0.f, a1 = 0.f, a2 = 0.f, a3 = 0.f;
#pragma unroll 8
        for (int k = 0; k < 512; k += 4) {
            a0 = fmaf(ls[k + 0], wr[k + 0], a0);
            a1 = fmaf(ls[k + 1], wr[k + 1], a1);
            a2 = fmaf(ls[k + 2], wr[k + 2], a2);
            a3 = fmaf(ls[k + 3], wr[k + 3], a3);
        }
        g_ef[t * TT + tid] = expf(a0 + a1 + a2 + a3 + b_out[tid]);
    }
}

// ---------------- k4: CRF linear-domain scans ----------------
__global__ __launch_bounds__(32) void k4_crf(const float* __restrict__ trans) {
    const unsigned FULL = 0xffffffffu;
    int l = threadIdx.x;
    bool hiA = (l < 2);
    int row2 = 32 + (hiA ? l : 0);

    if (blockIdx.x == 0) {
        // forward
        float m0[TT], m1[TT];
#pragma unroll
        for (int i = 0; i < TT; i++) {
            m0[i] = expf(trans[l * TT + i]);
            m1[i] = expf(trans[row2 * TT + i]);
        }
        float a0 = 0.f;
        float a1 = (l == 0) ? 1.f : 0.f;  // START=32 lives on lane 0 of a1
        float invs = 1.f, kf = 0.f, Kcum = 0.f;
        for (int t = 0; t < LSEQ; t++) {
            float e0 = g_ef[t * TT + l];
            float e1 = g_ef[t * TT + row2];
            float sA = 0.f, sAh = 0.f;
#pragma unroll
            for (int i = 0; i < 32; i++) {
                float ai = __shfl_sync(FULL, a0, i);
                sA  = fmaf(m0[i], ai, sA);
                sAh = fmaf(m1[i], ai, sAh);
            }
            float a32 = __shfl_sync(FULL, a1, 0);
            float a33 = __shfl_sync(FULL, a1, 1);
            sA  = fmaf(m0[32], a32, fmaf(m0[33], a33, sA));
            sAh = fmaf(m1[32], a32, fmaf(m1[33], a33, sAh));

            float anew  = sA * e0 * invs;
            float anewh = sAh * e1 * invs;
            Kcum += kf;
            g_aS[t * TT + l] = anew;
            if (hiA) g_aS[t * TT + 32 + l] = anewh;
            if (l == 0) g_Ka[t] = Kcum;

            float mx = hiA ? fmaxf(anew, anewh) : anew;
#pragma unroll
            for (int d = 16; d >= 1; d >>= 1)
                mx = fmaxf(mx, __shfl_xor_sync(FULL, mx, d));
            int k = (__float_as_int(mx) >> 23) - 127;
            invs = __int_as_float((127 - k) << 23);
            kf = (float)k;
            a0 = anew; a1 = anewh;
        }
    } else {
        // backward
        float m0[TT], m1[TT];  // columns l and 32+l
#pragma unroll
        for (int i = 0; i < TT; i++) {
            m0[i] = expf(trans[i * TT + l]);
            m1[i] = expf(trans[i * TT + row2]);
        }
        float cs0 = 0.f, cs1 = 0.f;
#pragma unroll
        for (int i = 0; i < TT; i++) { cs0 += m0[i]; cs1 += m1[i]; }
        float b0 = cs0, b1 = cs1;
        g_bS[(LSEQ - 1) * TT + l] = b0;
        if (hiA) g_bS[(LSEQ - 1) * TT + 32 + l] = b1;
        if (l == 0) g_Kb[LSEQ - 1] = 0.f;

        float mx0 = hiA ? fmaxf(b0, b1) : b0;
#pragma unroll
        for (int d = 16; d >= 1; d >>= 1)
            mx0 = fmaxf(mx0, __shfl_xor_sync(FULL, mx0, d));
        int k0i = (__float_as_int(mx0) >> 23) - 127;
        float invs = __int_as_float((127 - k0i) << 23);
        float kf = (float)k0i, Kcum = 0.f;

        for (int t = LSEQ - 2; t >= 0; t--) {
            float bp  = b0 * g_ef[(t + 1) * TT + l];
            float bph = b1 * g_ef[(t + 1) * TT + row2];
            float sA = 0.f, sAh = 0.f;
#pragma unroll
            for (int i = 0; i < 32; i++) {
                float bi = __shfl_sync(FULL, bp, i);
                sA  = fmaf(m0[i], bi, sA);
                sAh = fmaf(m1[i], bi, sAh);
            }
            float b32 = __shfl_sync(FULL, bph, 0);
            float b33 = __shfl_sync(FULL, bph, 1);
            sA  = fmaf(m0[32], b32, fmaf(m0[33], b33, sA));
            sAh = fmaf(m1[32], b32, fmaf(m1[33], b33, sAh));

            float bnew  = sA * invs;
            float bnewh = sAh * invs;
            Kcum += kf;
            g_bS[t * TT + l] = bnew;
            if (hiA) g_bS[t * TT + 32 + l] = bnewh;
            if (l == 0) g_Kb[t] = Kcum;

            float mx = hiA ? fmaxf(bnew, bnewh) : bnew;
#pragma unroll
            for (int d = 16; d >= 1; d >>= 1)
                mx = fmaxf(mx, __shfl_xor_sync(FULL, mx, d));
            int k = (__float_as_int(mx) >> 23) - 127;
            invs = __int_as_float((127 - k) << 23);
            kf = (float)k;
            b0 = bnew; b1 = bnewh;
        }
    }
}

// ---------------- k5: scores + argmax ----------------
__global__ void k5_out(float* out, int out_size) {
    int t = blockIdx.x * blockDim.x + threadIdx.x;
    if (t >= LSEQ) return;
    float K = (g_Ka[t] + g_Kb[t]) * 0.69314718055994531f;
    float best = -1e30f;
    int bj = 0;
    bool wr_score = (out_size >= LSEQ * TT);
#pragma unroll 2
    for (int j = 0; j < TT; j++) {
        float s = logf(g_aS[t * TT + j]) + logf(g_bS[t * TT + j]) + K;
        if (wr_score) out[t * TT + j] = s;
        if (s > best) { best = s; bj = j; }
    }
    if (out_size >= LSEQ * TT + LSEQ) out[LSEQ * TT + t] = (float)bj;
    else if (!wr_score && out_size >= LSEQ) out[t] = (float)bj;
}

extern "C" void kernel_launch(void* const* d_in, const int* in_sizes, int n_in,
                              void* d_out, int out_size) {
    const int*   words = (const int*)  d_in[0];
    const float* embed = (const float*)d_in[1];
    const float* Wih_f = (const float*)d_in[2];
    const float* Whh_f = (const float*)d_in[3];
    const float* b_f   = (const float*)d_in[4];
    const float* Wih_b = (const float*)d_in[5];
    const float* Whh_b = (const float*)d_in[6];
    const float* b_b   = (const float*)d_in[7];
    const float* W_out = (const float*)d_in[8];
    const float* b_out = (const float*)d_in[9];
    const float* trans = (const float*)d_in[10];
    float* out = (float*)d_out;

    k0_fill<<<(out_size + 255) / 256, 256>>>(out, out_size);
    dim3 g1(LSEQ / 64, G4 / 64, 2);
    k1_gx<<<g1, 256>>>(words, embed, Wih_f, b_f, Wih_b, b_b);
    k2_lstm<<<16, 256>>>(Whh_f, Whh_b);
    k3_feats<<<LSEQ, 64>>>(W_out, b_out);
    k4_crf<<<2, 32>>>(trans);
    k5_out<<<(LSEQ + 255) / 256, 256>>>(out, out_size);
}

// round 7
// speedup vs baseline: 1.9910x; 1.9910x over previous
#include <cuda_runtime.h>
#include <cooperative_groups.h>
#include <math.h>
#include <stdint.h>

namespace cg = cooperative_groups;

#define LSEQ 8192
#define EDIM 256
#define HD 256
#define G4 1024
#define TT 34

// ---------------- static scratch ----------------
__device__ float g_Gx[2][LSEQ * G4];
__device__ float g_hs[2][LSEQ * HD];
__device__ float g_ef[LSEQ * TT + 64];
__device__ float g_aS[LSEQ * TT];
__device__ float g_bS[LSEQ * TT];
__device__ float g_Ka[LSEQ];
__device__ float g_Kb[LSEQ];

// ---------------- helpers ----------------
__device__ __forceinline__ void fma2(unsigned long long& d, unsigned long long a,
                                     unsigned long long b) {
    asm("fma.rn.f32x2 %0, %1, %2, %0;" : "+l"(d) : "l"(a), "l"(b));
}
__device__ __forceinline__ unsigned long long add2(unsigned long long a,
                                                   unsigned long long b) {
    unsigned long long d;
    asm("add.rn.f32x2 %0, %1, %2;" : "=l"(d) : "l"(a), "l"(b));
    return d;
}
__device__ __forceinline__ float hsum2(unsigned long long a) {
    float lo, hi;
    asm("mov.b64 {%0, %1}, %2;" : "=f"(lo), "=f"(hi) : "l"(a));
    return lo + hi;
}
__device__ __forceinline__ float sigm(float x) {
    return __fdividef(1.f, 1.f + __expf(-x));
}
__device__ __forceinline__ float tanh_(float x) {
    float e = __expf(2.f * x);
    return 1.f - __fdividef(2.f, e + 1.f);
}
__device__ __forceinline__ uint32_t smem_u32(const void* p) {
    return (uint32_t)__cvta_generic_to_shared(p);
}
__device__ __forceinline__ void mbar_init(uint32_t a, uint32_t cnt) {
    asm volatile("mbarrier.init.shared.b64 [%0], %1;" :: "r"(a), "r"(cnt) : "memory");
}
__device__ __forceinline__ void mbar_arrive_expect_tx(uint32_t a, uint32_t tx) {
    asm volatile("mbarrier.arrive.expect_tx.shared.b64 _, [%0], %1;"
                 :: "r"(a), "r"(tx) : "memory");
}
__device__ __forceinline__ void mbar_wait_parity(uint32_t addr, uint32_t parity) {
    uint32_t done;
    asm volatile(
        "{\n\t.reg .pred p;\n\t"
        "mbarrier.try_wait.parity.acquire.cta.shared::cta.b64 p, [%1], %2;\n\t"
        "selp.b32 %0, 1, 0, p;\n\t}"
        : "=r"(done) : "r"(addr), "r"(parity) : "memory");
    if (!done) {
        asm volatile(
            "{\n\t.reg .pred P1;\n\t"
            "WL_%=:\n\t"
            "mbarrier.try_wait.parity.acquire.cta.shared::cta.b64 P1, [%0], %1, 0x989680;\n\t"
            "@P1 bra.uni WD_%=;\n\t"
            "bra.uni WL_%=;\n\t"
            "WD_%=:\n\t}"
            :: "r"(addr), "r"(parity) : "memory");
    }
}
__device__ __forceinline__ uint32_t mapa_u32(uint32_t a, uint32_t r) {
    uint32_t d;
    asm("mapa.shared::cluster.u32 %0, %1, %2;" : "=r"(d) : "r"(a), "r"(r));
    return d;
}
__device__ __forceinline__ void st_async_u32(uint32_t raddr, uint32_t v, uint32_t rmbar) {
    asm volatile(
        "st.async.shared::cluster.mbarrier::complete_tx::bytes.u32 [%0], %1, [%2];"
        :: "r"(raddr), "r"(v), "r"(rmbar) : "memory");
}

// ---------------- k0: zero output ----------------
__global__ void k0_fill(float* out, int n) {
    int i = blockIdx.x * blockDim.x + threadIdx.x;
    if (i < n) out[i] = 0.f;
}

// ---------------- k1: input projection GEMM ----------------
__global__ __launch_bounds__(256) void k1_gx(
    const int* __restrict__ words, const float* __restrict__ embed,
    const float* __restrict__ Wih_f, const float* __restrict__ b_f,
    const float* __restrict__ Wih_b, const float* __restrict__ b_b) {
    int dir = blockIdx.z;
    const float* Wih = dir ? Wih_b : Wih_f;
    const float* bias = dir ? b_b : b_f;
    int t0 = blockIdx.x * 64, r0 = blockIdx.y * 64;

    __shared__ int ws_[64];
    __shared__ __align__(16) float sx[32][68];
    __shared__ __align__(16) float sw[32][68];

    int tid = threadIdx.x;
    int tx = tid & 15, ty = tid >> 4;
    if (tid < 64) ws_[tid] = words[t0 + tid];
    __syncthreads();

    float acc[4][4];
#pragma unroll
    for (int i = 0; i < 4; i++)
#pragma unroll
        for (int j = 0; j < 4; j++) acc[i][j] = 0.f;

    for (int k0 = 0; k0 < EDIM; k0 += 32) {
#pragma unroll
        for (int rep = 0; rep < 2; rep++) {
            int lin = tid + rep * 256;
            int row = lin >> 3;
            int kq = lin & 7;
            float4 xv = *(const float4*)&embed[(size_t)ws_[row] * EDIM + k0 + kq * 4];
            sx[kq * 4 + 0][row] = xv.x; sx[kq * 4 + 1][row] = xv.y;
            sx[kq * 4 + 2][row] = xv.z; sx[kq * 4 + 3][row] = xv.w;
            float4 wv = *(const float4*)&Wih[(size_t)(r0 + row) * EDIM + k0 + kq * 4];
            sw[kq * 4 + 0][row] = wv.x; sw[kq * 4 + 1][row] = wv.y;
            sw[kq * 4 + 2][row] = wv.z; sw[kq * 4 + 3][row] = wv.w;
        }
        __syncthreads();
#pragma unroll
        for (int kk = 0; kk < 32; kk++) {
            float4 a = *(const float4*)&sx[kk][tx * 4];
            float4 b = *(const float4*)&sw[kk][ty * 4];
            float av[4] = {a.x, a.y, a.z, a.w};
            float bv[4] = {b.x, b.y, b.z, b.w};
#pragma unroll
            for (int i = 0; i < 4; i++)
#pragma unroll
                for (int j = 0; j < 4; j++)
                    acc[i][j] = fmaf(av[i], bv[j], acc[i][j]);
        }
        __syncthreads();
    }
    float bj[4];
#pragma unroll
    for (int j = 0; j < 4; j++) bj[j] = bias[r0 + ty * 4 + j];
    float* outp = g_Gx[dir];
#pragma unroll
    for (int i = 0; i < 4; i++)
#pragma unroll
        for (int j = 0; j < 4; j++)
            outp[(size_t)(t0 + tx * 4 + i) * G4 + (r0 + ty * 4 + j)] = acc[i][j] + bj[j];
}

// ---------------- k2: bidirectional LSTM, mbarrier/st.async pipeline ----------------
__global__ __launch_bounds__(256, 1) __cluster_dims__(8, 1, 1)
void k2_lstm(const float* __restrict__ Whh_f, const float* __restrict__ Whh_b) {
    cg::cluster_group cluster = cg::this_cluster();
    int rank = (int)cluster.block_rank();
    int dir = (blockIdx.x >= 8) ? 1 : 0;
    const float* Whh = dir ? Whh_b : Whh_f;

    __shared__ __align__(16) float h_buf[2][HD];
    __shared__ float red[256];
    __shared__ __align__(8) unsigned long long mbar_s[2];

    int tid = threadIdx.x;
    int w = tid >> 5, l = tid & 31;
    int g = w & 3, khalf = w >> 2;
    int j0 = rank * 32;
    int R = g * 256 + j0 + l;

    unsigned long long w2[64];
    {
        const unsigned long long* wp =
            (const unsigned long long*)(Whh + (size_t)R * HD + khalf * 128);
#pragma unroll
        for (int k = 0; k < 64; k++) w2[k] = wp[k];
    }

    h_buf[0][tid] = 0.f;
    h_buf[1][tid] = 0.f;

    uint32_t mb0 = smem_u32(&mbar_s[0]);
    uint32_t mb1 = smem_u32(&mbar_s[1]);
    uint32_t slot0 = smem_u32(&h_buf[0][j0 + l]);
    uint32_t slot1 = smem_u32(&h_buf[1][j0 + l]);

    if (tid == 0) {
        mbar_init(mb0, 1);
        mbar_init(mb1, 1);
        mbar_arrive_expect_tx(mb0, 1024);   // arms use at t=2
        mbar_arrive_expect_tx(mb1, 1024);   // arms use at t=1
    }
    __syncthreads();
    cluster.sync();   // all barriers armed before any st.async can land

    float c = 0.f;
    const float* Gx = g_Gx[dir];
    float* hsout = g_hs[dir];

    // prefetch gx for t=0
    float gx0 = 0.f, gx1 = 0.f, gx2 = 0.f, gx3 = 0.f;
    if (w == 0) {
        int tt0 = dir ? (LSEQ - 1) : 0;
        const float* gp = Gx + (size_t)tt0 * G4 + j0 + l;
        gx0 = gp[0]; gx1 = gp[256]; gx2 = gp[512]; gx3 = gp[768];
    }
    int ph0 = 0, ph1 = 0;

    for (int t = 0; t < LSEQ; t++) {
        int buf = t & 1;
        int nb = buf ^ 1;
        int tt = dir ? (LSEQ - 1 - t) : t;

        // prefetch gx for t+1 (independent of the wait; ~1 step of cover)
        float ngx0 = 0.f, ngx1 = 0.f, ngx2 = 0.f, ngx3 = 0.f;
        if (w == 0 && t + 1 < LSEQ) {
            int tn = dir ? (LSEQ - 2 - t) : (t + 1);
            const float* gp = Gx + (size_t)tn * G4 + j0 + l;
            ngx0 = gp[0]; ngx1 = gp[256]; ngx2 = gp[512]; ngx3 = gp[768];
        }

        if (t > 0) {
            uint32_t mba = buf ? mb1 : mb0;
            uint32_t ph = buf ? ph1 : ph0;
            mbar_wait_parity(mba, ph);
            if (buf) ph1 ^= 1; else ph0 ^= 1;
            if (tid == 0) mbar_arrive_expect_tx(mba, 1024);  // re-arm for t+2
        }

        // matvec: 32 LDS.128 + 64 FFMA2 per thread
        const ulonglong2* hp = (const ulonglong2*)&h_buf[buf][khalf * 128];
        unsigned long long a0 = 0ull, a1 = 0ull, a2 = 0ull, a3 = 0ull;
#pragma unroll
        for (int k = 0; k < 32; k += 4) {
            ulonglong2 h0 = hp[k], h1 = hp[k + 1], h2 = hp[k + 2], h3 = hp[k + 3];
            fma2(a0, w2[2 * k + 0], h0.x); fma2(a1, w2[2 * k + 1], h0.y);
            fma2(a2, w2[2 * k + 2], h1.x); fma2(a3, w2[2 * k + 3], h1.y);
            fma2(a0, w2[2 * k + 4], h2.x); fma2(a1, w2[2 * k + 5], h2.y);
            fma2(a2, w2[2 * k + 6], h3.x); fma2(a3, w2[2 * k + 7], h3.y);
        }
        red[tid] = hsum2(add2(add2(a0, a1), add2(a2, a3)));
        __syncthreads();

        if (w == 0) {
            float gi = red[l]       + red[128 + l] + gx0;
            float gf = red[32 + l]  + red[160 + l] + gx1;
            float gg = red[64 + l]  + red[192 + l] + gx2;
            float go = red[96 + l]  + red[224 + l] + gx3;
            float i_ = sigm(gi), f_ = sigm(gf), g_ = tanh_(gg), o_ = sigm(go);
            c = f_ * c + i_ * g_;
            float h = o_ * tanh_(c);
            hsout[(size_t)tt * HD + j0 + l] = h;

            uint32_t val = __float_as_uint(h);
            uint32_t la = nb ? slot1 : slot0;
            uint32_t lm = nb ? mb1 : mb0;
#pragma unroll
            for (int p = 0; p < 8; p++) {
                uint32_t ra = mapa_u32(la, (uint32_t)p);
                uint32_t rm = mapa_u32(lm, (uint32_t)p);
                st_async_u32(ra, val, rm);
            }
        }
        gx0 = ngx0; gx1 = ngx1; gx2 = ngx2; gx3 = ngx3;
    }
    cluster.sync();  // don't exit while peers' st.async may be in flight
}

// ---------------- k3: feats + exp (smem-tiled, k-split, 64 t / block) ----------------
__global__ __launch_bounds__(256) void k3_feats(const float* __restrict__ W_out,
                                                const float* __restrict__ b_out) {
    __shared__ __align__(16) float Ws[256 * 36];   // [k][j], k-half
    __shared__ __align__(16) float hsm[256];
    __shared__ float redx[8 * 36];
    __shared__ float part[64 * 36];

    int tid = threadIdx.x;
    int kg = tid >> 5, l = tid & 31;
    int j2 = 32 + (l & 1);
    int tbase = blockIdx.x * 64;

    for (int idx = tid; idx < 64 * 36; idx += 256) part[idx] = 0.f;

    for (int kh = 0; kh < 2; kh++) {
        __syncthreads();
        for (int idx = tid; idx < 34 * 256; idx += 256) {
            int j = idx >> 8, k = idx & 255;
            Ws[k * 36 + j] = W_out[j * 512 + kh * 256 + k];
        }
        const float* hsrc = g_hs[kh];
        for (int tt6 = 0; tt6 < 64; tt6++) {
            int t = tbase + tt6;
            __syncthreads();
            if (tid < 256) hsm[tid] = hsrc[(size_t)t * HD + tid];
            __syncthreads();
            float a0 = 0.f, a1 = 0.f, b0 = 0.f, b1 = 0.f;
            int kb = kg * 32;
#pragma unroll
            for (int k = kb; k < kb + 32; k += 8) {
                float4 hv = *(const float4*)&hsm[k];
                const float* wr = &Ws[k * 36];
                a0 = fmaf(hv.x, wr[l], a0);        a1 = fmaf(hv.x, wr[j2], a1);
                a0 = fmaf(hv.y, wr[36 + l], a0);   a1 = fmaf(hv.y, wr[36 + j2], a1);
                a0 = fmaf(hv.z, wr[72 + l], a0);   a1 = fmaf(hv.z, wr[72 + j2], a1);
                a0 = fmaf(hv.w, wr[108 + l], a0);  a1 = fmaf(hv.w, wr[108 + j2], a1);
                float4 hw = *(const float4*)&hsm[k + 4];
                const float* ws2 = &Ws[(k + 4) * 36];
                b0 = fmaf(hw.x, ws2[l], b0);        b1 = fmaf(hw.x, ws2[j2], b1);
                b0 = fmaf(hw.y, ws2[36 + l], b0);   b1 = fmaf(hw.y, ws2[36 + j2], b1);
                b0 = fmaf(hw.z, ws2[72 + l], b0);   b1 = fmaf(hw.z, ws2[72 + j2], b1);
                b0 = fmaf(hw.w, ws2[108 + l], b0);  b1 = fmaf(hw.w, ws2[108 + j2], b1);
            }
            redx[kg * 36 + l] = a0 + b0;
            if (l < 2) redx[kg * 36 + 32 + l] = a1 + b1;
            __syncthreads();
            if (tid < 34) {
                float s = 0.f;
#pragma unroll
                for (int q = 0; q < 8; q++) s += redx[q * 36 + tid];
                part[tt6 * 36 + tid] += s;
            }
        }
    }
    __syncthreads();
    for (int idx = tid; idx < 64 * 34; idx += 256) {
        int tt6 = idx / 34, j = idx % 34;
        g_ef[(size_t)(tbase + tt6) * TT + j] = __expf(part[tt6 * 36 + j] + b_out[j]);
    }
}

// ---------------- k4: CRF linear-domain scans ----------------
__global__ __launch_bounds__(32) void k4_crf(const float* __restrict__ trans) {
    const unsigned FULL = 0xffffffffu;
    int l = threadIdx.x;
    bool hiA = (l < 2);
    int row2 = 32 + (hiA ? l : 0);

    if (blockIdx.x == 0) {
        // forward
        float m0[TT], m1[TT];
#pragma unroll
        for (int i = 0; i < TT; i++) {
            m0[i] = expf(trans[l * TT + i]);
            m1[i] = expf(trans[row2 * TT + i]);
        }
        float a0 = 0.f;
        float a1 = (l == 0) ? 1.f : 0.f;
        float invs = 1.f, kf = 0.f, Kcum = 0.f;
        float e0 = g_ef[l];
        float e1 = g_ef[row2];
        for (int t = 0; t < LSEQ; t++) {
            float en0 = g_ef[(t + 1) * TT + l];       // pad-safe at t=LSEQ-1
            float en1 = g_ef[(t + 1) * TT + row2];
            float s0 = 0.f, s1 = 0.f, s2 = 0.f, s3 = 0.f;
            float h0 = 0.f, h1 = 0.f, h2 = 0.f, h3 = 0.f;
#pragma unroll
            for (int i = 0; i < 32; i += 4) {
                float v0 = __shfl_sync(FULL, a0, i);
                float v1 = __shfl_sync(FULL, a0, i + 1);
                float v2 = __shfl_sync(FULL, a0, i + 2);
                float v3 = __shfl_sync(FULL, a0, i + 3);
                s0 = fmaf(m0[i], v0, s0);     h0 = fmaf(m1[i], v0, h0);
                s1 = fmaf(m0[i + 1], v1, s1); h1 = fmaf(m1[i + 1], v1, h1);
                s2 = fmaf(m0[i + 2], v2, s2); h2 = fmaf(m1[i + 2], v2, h2);
                s3 = fmaf(m0[i + 3], v3, s3); h3 = fmaf(m1[i + 3], v3, h3);
            }
            float a32 = __shfl_sync(FULL, a1, 0);
            float a33 = __shfl_sync(FULL, a1, 1);
            s0 = fmaf(m0[32], a32, s0); s1 = fmaf(m0[33], a33, s1);
            h0 = fmaf(m1[32], a32, h0); h1 = fmaf(m1[33], a33, h1);
            float sA  = (s0 + s1) + (s2 + s3);
            float sAh = (h0 + h1) + (h2 + h3);

            float anew  = sA * e0 * invs;
            float anewh = sAh * e1 * invs;
            Kcum += kf;
            g_aS[t * TT + l] = anew;
            if (hiA) g_aS[t * TT + 32 + l] = anewh;
            if (l == 0) g_Ka[t] = Kcum;

            float mx = hiA ? fmaxf(anew, anewh) : anew;
#pragma unroll
            for (int d = 16; d >= 1; d >>= 1)
                mx = fmaxf(mx, __shfl_xor_sync(FULL, mx, d));
            int k = (__float_as_int(mx) >> 23) - 127;
            invs = __int_as_float((127 - k) << 23);
            kf = (float)k;
            a0 = anew; a1 = anewh; e0 = en0; e1 = en1;
        }
    } else {
        // backward
        float m0[TT], m1[TT];
#pragma unroll
        for (int i = 0; i < TT; i++) {
            m0[i] = expf(trans[i * TT + l]);
            m1[i] = expf(trans[i * TT + row2]);
        }
        float cs0 = 0.f, cs1 = 0.f;
#pragma unroll
        for (int i = 0; i < TT; i++) { cs0 += m0[i]; cs1 += m1[i]; }
        float b0 = cs0, b1 = cs1;
        g_bS[(LSEQ - 1) * TT + l] = b0;
        if (hiA) g_bS[(LSEQ - 1) * TT + 32 + l] = b1;
        if (l == 0) g_Kb[LSEQ - 1] = 0.f;

        float mx0 = hiA ? fmaxf(b0, b1) : b0;
#pragma unroll
        for (int d = 16; d >= 1; d >>= 1)
            mx0 = fmaxf(mx0, __shfl_xor_sync(FULL, mx0, d));
        int k0i = (__float_as_int(mx0) >> 23) - 127;
        float invs = __int_as_float((127 - k0i) << 23);
        float kf = (float)k0i, Kcum = 0.f;

        float ec0 = g_ef[(LSEQ - 1) * TT + l];
        float ec1 = g_ef[(LSEQ - 1) * TT + row2];
        for (int t = LSEQ - 2; t >= 0; t--) {
            float en0 = g_ef[t * TT + l];      // for next iteration
            float en1 = g_ef[t * TT + row2];
            float bp  = b0 * ec0;
            float bph = b1 * ec1;
            float s0 = 0.f, s1 = 0.f, s2 = 0.f, s3 = 0.f;
            float h0 = 0.f, h1 = 0.f, h2 = 0.f, h3 = 0.f;
#pragma unroll
            for (int i = 0; i < 32; i += 4) {
                float v0 = __shfl_sync(FULL, bp, i);
                float v1 = __shfl_sync(FULL, bp, i + 1);
                float v2 = __shfl_sync(FULL, bp, i + 2);
                float v3 = __shfl_sync(FULL, bp, i + 3);
                s0 = fmaf(m0[i], v0, s0);     h0 = fmaf(m1[i], v0, h0);
                s1 = fmaf(m0[i + 1], v1, s1); h1 = fmaf(m1[i + 1], v1, h1);
                s2 = fmaf(m0[i + 2], v2, s2); h2 = fmaf(m1[i + 2], v2, h2);
                s3 = fmaf(m0[i + 3], v3, s3); h3 = fmaf(m1[i + 3], v3, h3);
            }
            float b32 = __shfl_sync(FULL, bph, 0);
            float b33 = __shfl_sync(FULL, bph, 1);
            s0 = fmaf(m0[32], b32, s0); s1 = fmaf(m0[33], b33, s1);
            h0 = fmaf(m1[32], b32, h0); h1 = fmaf(m1[33], b33, h1);
            float sA  = (s0 + s1) + (s2 + s3);
            float sAh = (h0 + h1) + (h2 + h3);

            float bnew  = sA * invs;
            float bnewh = sAh * invs;
            Kcum += kf;
            g_bS[t * TT + l] = bnew;
            if (hiA) g_bS[t * TT + 32 + l] = bnewh;
            if (l == 0) g_Kb[t] = Kcum;

            float mx = hiA ? fmaxf(bnew, bnewh) : bnew;
#pragma unroll
            for (int d = 16; d >= 1; d >>= 1)
                mx = fmaxf(mx, __shfl_xor_sync(FULL, mx, d));
            int k = (__float_as_int(mx) >> 23) - 127;
            invs = __int_as_float((127 - k) << 23);
            kf = (float)k;
            b0 = bnew; b1 = bnewh; ec0 = en0; ec1 = en1;
        }
    }
}

// ---------------- k5: scores + argmax ----------------
__global__ void k5_out(float* out, int out_size) {
    int t = blockIdx.x * blockDim.x + threadIdx.x;
    if (t >= LSEQ) return;
    float K = (g_Ka[t] + g_Kb[t]) * 0.69314718055994531f;
    float best = -1e30f;
    int bj = 0;
    bool wr_score = (out_size >= LSEQ * TT);
#pragma unroll 2
    for (int j = 0; j < TT; j++) {
        float s = logf(g_aS[t * TT + j]) + logf(g_bS[t * TT + j]) + K;
        if (wr_score) out[t * TT + j] = s;
        if (s > best) { best = s; bj = j; }
    }
    if (out_size >= LSEQ * TT + LSEQ) out[LSEQ * TT + t] = (float)bj;
    else if (!wr_score && out_size >= LSEQ) out[t] = (float)bj;
}

extern "C" void kernel_launch(void* const* d_in, const int* in_sizes, int n_in,
                              void* d_out, int out_size) {
    const int*   words = (const int*)  d_in[0];
    const float* embed = (const float*)d_in[1];
    const float* Wih_f = (const float*)d_in[2];
    const float* Whh_f = (const float*)d_in[3];
    const float* b_f   = (const float*)d_in[4];
    const float* Wih_b = (const float*)d_in[5];
    const float* Whh_b = (const float*)d_in[6];
    const float* b_b   = (const float*)d_in[7];
    const float* W_out = (const float*)d_in[8];
    const float* b_out = (const float*)d_in[9];
    const float* trans = (const float*)d_in[10];
    float* out = (float*)d_out;

    k0_fill<<<(out_size + 255) / 256, 256>>>(out, out_size);
    dim3 g1(LSEQ / 64, G4 / 64, 2);
    k1_gx<<<g1, 256>>>(words, embed, Wih_f, b_f, Wih_b, b_b);
    k2_lstm<<<16, 256>>>(Whh_f, Whh_b);
    k3_feats<<<LSEQ / 64, 256>>>(W_out, b_out);
    k4_crf<<<2, 32>>>(trans);
    k5_out<<<(LSEQ + 255) / 256, 256>>>(out, out_size);
}